// round 16
// baseline (speedup 1.0000x reference)
#include <cuda_runtime.h>
#include <cuda_bf16.h>
#include <cstdint>

#define NUM_C 46
#define WARPS 7
#define THREADS (WARPS * 32)               // 224
#define WARP_ROWS 16
#define WTILE_FLOATS (WARP_ROWS * NUM_C)   // 736
#define WTILE_VEC (WTILE_FLOATS / 4)       // 184
#define BLOCKS 740                         // 5 per SM on 148 SMs
#define NPART (3 * NUM_C)                  // 138: [col | tp | cnt]

__device__ float g_sum[NPART];             // zeroed at load; each launch restores it
__device__ unsigned int g_ticket = 0;

__device__ __forceinline__ void cp_async16(void* smem, const void* gmem) {
    uint32_t s = (uint32_t)__cvta_generic_to_shared(smem);
    asm volatile("cp.async.cg.shared.global [%0], [%1], 16;\n" :: "r"(s), "l"(gmem));
}
__device__ __forceinline__ void cp_async4(void* smem, const void* gmem) {
    uint32_t s = (uint32_t)__cvta_generic_to_shared(smem);
    asm volatile("cp.async.ca.shared.global [%0], [%1], 4;\n" :: "r"(s), "l"(gmem));
}
#define CP_COMMIT() asm volatile("cp.async.commit_group;\n" ::: "memory")
#define CP_WAIT(n)  asm volatile("cp.async.wait_group %0;\n" :: "n"(n) : "memory")

__global__ __launch_bounds__(THREADS, 5) void accum_kernel(
    const float* __restrict__ y_pred,
    const int* __restrict__ y_true,
    int n_rows,
    float* __restrict__ out)
{
    __shared__ float s_buf[WARPS][2][WTILE_FLOATS];   // 41216 B
    __shared__ float s_tp[NUM_C];
    __shared__ float s_cnt[NUM_C];
    __shared__ float s_col[NUM_C];
    __shared__ unsigned int s_rank;

    const int t    = threadIdx.x;
    const int wid  = t >> 5;
    const int lane = t & 31;

    if (t < NUM_C) {
        s_tp[t]  = 0.0f;
        s_cnt[t] = 0.0f;
        s_col[t] = 0.0f;
    }

    const int num_wt  = (n_rows + WARP_ROWS - 1) / WARP_ROWS;
    const int wstride = gridDim.x * WARPS;

    // per-warp async copy of one 16-row tile into buffer b
    auto issue = [&](int wt_i, int b) {
        const int row0 = wt_i * WARP_ROWS;
        const int rows = min(WARP_ROWS, n_rows - row0);
        if (rows == WARP_ROWS) {
            const float4* src = reinterpret_cast<const float4*>(y_pred) +
                                (size_t)row0 * NUM_C / 4;
            float4* dst = reinterpret_cast<float4*>(s_buf[wid][b]);
            #pragma unroll
            for (int i = lane; i < WTILE_VEC; i += 32)
                cp_async16(&dst[i], &src[i]);
        } else {
            const int n_el = rows * NUM_C;
            const float* src = y_pred + (size_t)row0 * NUM_C;
            for (int i = lane; i < n_el; i += 32)
                cp_async4(&s_buf[wid][b][i], &src[i]);
        }
        CP_COMMIT();
    };

    int wt = blockIdx.x * WARPS + wid;
    if (wt < num_wt) issue(wt, 0);
    __syncthreads();       // one-time: covers s_tp/s_cnt/s_col zero-init

    float acc0 = 0.0f;     // class = lane        (0..31)
    float acc1 = 0.0f;     // class = 32 + lane   (lanes 0..13)

    int b = 0;
    for (; wt < num_wt; wt += wstride) {
        const int row0 = wt * WARP_ROWS;
        const int rows_here = min(WARP_ROWS, n_rows - row0);

        // label load above the pipeline wait: its latency overlaps the
        // cp.async wait + column-sum chain
        int lab = 0;
        if (lane < rows_here)
            lab = y_true[row0 + lane];

        const int nxt = wt + wstride;
        if (nxt < num_wt) {
            issue(nxt, b ^ 1);
            CP_WAIT(1);          // current tile arrived; next may be in flight
        } else {
            CP_WAIT(0);
        }
        __syncwarp();            // all lanes' copies for this tile complete

        const float* tl = s_buf[wid][b];

        if (rows_here == WARP_ROWS) {
            #pragma unroll
            for (int r = 0; r < WARP_ROWS; r++) {
                acc0 += tl[r * NUM_C + lane];
                if (lane < NUM_C - 32)
                    acc1 += tl[r * NUM_C + 32 + lane];
            }
        } else {
            for (int r = 0; r < rows_here; r++) {
                acc0 += tl[r * NUM_C + lane];
                if (lane < NUM_C - 32)
                    acc1 += tl[r * NUM_C + 32 + lane];
            }
        }

        if (lane < rows_here) {
            atomicAdd(&s_tp[lab], tl[lane * NUM_C + lab]);
            atomicAdd(&s_cnt[lab], 1.0f);
        }
        __syncwarp();            // lanes done reading buf b before its reuse
        b ^= 1;
    }

    // flush per-lane class accumulators (7 warps contend lightly per class)
    atomicAdd(&s_col[lane], acc0);
    if (lane < NUM_C - 32)
        atomicAdd(&s_col[32 + lane], acc1);
    __syncthreads();

    // flush block partials straight to the global accumulators
    if (t < NPART) {
        float v = (t < NUM_C) ? s_col[t]
                : (t < 2 * NUM_C) ? s_tp[t - NUM_C]
                : s_cnt[t - 2 * NUM_C];
        atomicAdd(&g_sum[t], v);
    }
    __threadfence();
    __syncthreads();

    if (t == 0)
        s_rank = atomicAdd(&g_ticket, 1u);
    __syncthreads();

    if (s_rank == (unsigned)(gridDim.x - 1)) {
        // last block: all other blocks' atomics are globally visible
        __shared__ float s_f1[NUM_C];
        const float EPS = 1e-7f;
        volatile float* gs = g_sum;
        if (t < NUM_C) {
            float col_sum = gs[t];                // tp + fp
            float tp      = gs[NUM_C + t];
            float cnt     = gs[2 * NUM_C + t];    // tp + fn
            float precision = tp / (col_sum + EPS);
            float recall    = tp / (cnt + EPS);
            float f1 = 2.0f * precision * recall / (precision + recall + EPS);
            f1 = fminf(fmaxf(f1, EPS), 1.0f - EPS);
            s_f1[t] = f1;
        }
        __syncthreads();
        if (t == 0) {
            float sm = 0.0f;
            #pragma unroll
            for (int i = 0; i < NUM_C; i++) sm += s_f1[i];
            out[0] = 1.0f - sm / (float)NUM_C;
        }
        __syncthreads();
        // restore state for the next (graph-replayed) launch
        if (t < NPART) g_sum[t] = 0.0f;
        if (t == 0) g_ticket = 0u;
        __threadfence();
    }
}

extern "C" void kernel_launch(void* const* d_in, const int* in_sizes, int n_in,
                              void* d_out, int out_size) {
    const float* y_pred = (const float*)d_in[0];
    const int*   y_true = (const int*)d_in[1];
    float* out = (float*)d_out;

    const int n_rows = in_sizes[0] / NUM_C;   // derive from y_pred element count

    accum_kernel<<<BLOCKS, THREADS>>>(y_pred, y_true, n_rows, out);
}

// round 17
// speedup vs baseline: 1.0337x; 1.0337x over previous
#include <cuda_runtime.h>
#include <cuda_bf16.h>
#include <cstdint>

#define NUM_C 46
#define WARPS 8
#define THREADS (WARPS * 32)
#define WARP_ROWS 16
#define WTILE_FLOATS (WARP_ROWS * NUM_C)   // 736
#define WTILE_VEC (WTILE_FLOATS / 4)       // 184
#define BLOCKS 592                         // 4 per SM on 148 SMs (smem-limited)
#define NPART (3 * NUM_C)                  // 138: [col | tp | cnt]

__device__ float g_sum[NPART];             // zeroed at load; each launch restores it
__device__ unsigned int g_ticket = 0;

__device__ __forceinline__ void cp_async16(void* smem, const void* gmem) {
    uint32_t s = (uint32_t)__cvta_generic_to_shared(smem);
    asm volatile("cp.async.cg.shared.global [%0], [%1], 16;\n" :: "r"(s), "l"(gmem));
}
__device__ __forceinline__ void cp_async4(void* smem, const void* gmem) {
    uint32_t s = (uint32_t)__cvta_generic_to_shared(smem);
    asm volatile("cp.async.ca.shared.global [%0], [%1], 4;\n" :: "r"(s), "l"(gmem));
}
#define CP_COMMIT() asm volatile("cp.async.commit_group;\n" ::: "memory")
#define CP_WAIT(n)  asm volatile("cp.async.wait_group %0;\n" :: "n"(n) : "memory")

__global__ __launch_bounds__(THREADS) void accum_kernel(
    const float* __restrict__ y_pred,
    const int* __restrict__ y_true,
    int n_rows,
    float* __restrict__ out)
{
    __shared__ float s_buf[WARPS][2][WTILE_FLOATS];   // 47104 B
    __shared__ float s_tp[NUM_C];
    __shared__ float s_cnt[NUM_C];
    __shared__ float s_col[NUM_C];
    __shared__ unsigned int s_rank;

    const int t    = threadIdx.x;
    const int wid  = t >> 5;
    const int lane = t & 31;

    if (t < NUM_C) {
        s_tp[t]  = 0.0f;
        s_cnt[t] = 0.0f;
        s_col[t] = 0.0f;
    }

    const int num_wt  = (n_rows + WARP_ROWS - 1) / WARP_ROWS;
    const int wstride = gridDim.x * WARPS;

    // per-warp async copy of one 16-row tile into buffer b
    auto issue = [&](int wt_i, int b) {
        const int row0 = wt_i * WARP_ROWS;
        const int rows = min(WARP_ROWS, n_rows - row0);
        if (rows == WARP_ROWS) {
            const float4* src = reinterpret_cast<const float4*>(y_pred) +
                                (size_t)row0 * NUM_C / 4;
            float4* dst = reinterpret_cast<float4*>(s_buf[wid][b]);
            #pragma unroll
            for (int i = lane; i < WTILE_VEC; i += 32)
                cp_async16(&dst[i], &src[i]);
        } else {
            const int n_el = rows * NUM_C;
            const float* src = y_pred + (size_t)row0 * NUM_C;
            for (int i = lane; i < n_el; i += 32)
                cp_async4(&s_buf[wid][b][i], &src[i]);
        }
        CP_COMMIT();
    };

    int wt = blockIdx.x * WARPS + wid;
    if (wt < num_wt) issue(wt, 0);
    __syncthreads();       // one-time: covers s_tp/s_cnt/s_col zero-init

    float acc0 = 0.0f;     // class = lane        (0..31)
    float acc1 = 0.0f;     // class = 32 + lane   (lanes 0..13)

    int b = 0;
    for (; wt < num_wt; wt += wstride) {
        const int row0 = wt * WARP_ROWS;
        const int rows_here = min(WARP_ROWS, n_rows - row0);

        // hoist label load ABOVE the pipeline wait: its DRAM/L2 latency
        // overlaps the cp.async wait + column-sum chain instead of being
        // exposed before the shared atomics.
        int lab = 0;
        if (lane < rows_here)
            lab = y_true[row0 + lane];

        const int nxt = wt + wstride;
        if (nxt < num_wt) {
            issue(nxt, b ^ 1);
            CP_WAIT(1);          // current tile arrived; next may be in flight
        } else {
            CP_WAIT(0);
        }
        __syncwarp();            // all lanes' copies for this tile complete

        const float* tl = s_buf[wid][b];

        if (rows_here == WARP_ROWS) {
            #pragma unroll
            for (int r = 0; r < WARP_ROWS; r++) {
                acc0 += tl[r * NUM_C + lane];
                if (lane < NUM_C - 32)
                    acc1 += tl[r * NUM_C + 32 + lane];
            }
        } else {
            for (int r = 0; r < rows_here; r++) {
                acc0 += tl[r * NUM_C + lane];
                if (lane < NUM_C - 32)
                    acc1 += tl[r * NUM_C + 32 + lane];
            }
        }

        if (lane < rows_here) {
            atomicAdd(&s_tp[lab], tl[lane * NUM_C + lab]);
            atomicAdd(&s_cnt[lab], 1.0f);
        }
        __syncwarp();
        b ^= 1;
    }

    // flush per-lane class accumulators (8 warps contend lightly per class)
    atomicAdd(&s_col[lane], acc0);
    if (lane < NUM_C - 32)
        atomicAdd(&s_col[32 + lane], acc1);
    __syncthreads();

    // flush block partials straight to the global accumulators
    if (t < NPART) {
        float v = (t < NUM_C) ? s_col[t]
                : (t < 2 * NUM_C) ? s_tp[t - NUM_C]
                : s_cnt[t - 2 * NUM_C];
        atomicAdd(&g_sum[t], v);
    }
    __threadfence();
    __syncthreads();

    if (t == 0)
        s_rank = atomicAdd(&g_ticket, 1u);
    __syncthreads();

    if (s_rank == (unsigned)(gridDim.x - 1)) {
        // last block: all other blocks' atomics are globally visible
        __shared__ float s_f1[NUM_C];
        const float EPS = 1e-7f;
        volatile float* gs = g_sum;
        if (t < NUM_C) {
            float col_sum = gs[t];                // tp + fp
            float tp      = gs[NUM_C + t];
            float cnt     = gs[2 * NUM_C + t];    // tp + fn
            float precision = tp / (col_sum + EPS);
            float recall    = tp / (cnt + EPS);
            float f1 = 2.0f * precision * recall / (precision + recall + EPS);
            f1 = fminf(fmaxf(f1, EPS), 1.0f - EPS);
            s_f1[t] = f1;
        }
        __syncthreads();
        if (t == 0) {
            float sm = 0.0f;
            #pragma unroll
            for (int i = 0; i < NUM_C; i++) sm += s_f1[i];
            out[0] = 1.0f - sm / (float)NUM_C;
        }
        __syncthreads();
        // restore state for the next (graph-replayed) launch
        if (t < NPART) g_sum[t] = 0.0f;
        if (t == 0) g_ticket = 0u;
        __threadfence();
    }
}

extern "C" void kernel_launch(void* const* d_in, const int* in_sizes, int n_in,
                              void* d_out, int out_size) {
    const float* y_pred = (const float*)d_in[0];
    const int*   y_true = (const int*)d_in[1];
    float* out = (float*)d_out;

    const int n_rows = in_sizes[0] / NUM_C;   // derive from y_pred element count

    accum_kernel<<<BLOCKS, THREADS>>>(y_pred, y_true, n_rows, out);
}